// round 3
// baseline (speedup 1.0000x reference)
#include <cuda_runtime.h>
#include <cstdint>

#define NN 8192
#define EE 262144
#define IND 128
#define HD 256

// ---------------- scratch (static device globals; referenced ONLY in device code) ----------------
__device__ int   g_count[NN];
__device__ int   g_cursor[NN];
__device__ int   g_row[NN + 1];
__device__ int   g_csr[EE];
__device__ float g_dinv[NN];
__device__ float g_xs[NN * IND];     // scaled input features
__device__ float g_agg[NN * HD];     // aggregation output (<=256 cols used)
__device__ float g_h[NN * HD];       // layer output (relu)
__device__ float g_hs[NN * HD];      // layer output * dinv (for next gather)
__device__ float g_u[HD], g_v[HD];
__device__ float g_a[NN], g_b[NN];
__device__ float g_ca, g_cb;
__device__ int   g_i32;              // edge_index dtype flag

// ---------------- f32x2 helpers ----------------
typedef unsigned long long u64;

__device__ __forceinline__ u64 pk2(float x, float y) {
    u64 r; asm("mov.b64 %0, {%1,%2};" : "=l"(r) : "f"(x), "f"(y)); return r;
}
__device__ __forceinline__ void fma2(u64 &d, u64 a, u64 b) {
    asm("fma.rn.f32x2 %0, %1, %2, %0;" : "+l"(d) : "l"(a), "l"(b));
}
__device__ __forceinline__ float2 up2(u64 v) {
    float2 r; asm("mov.b64 {%0,%1}, %2;" : "=f"(r.x), "=f"(r.y) : "l"(v)); return r;
}

// ---------------- graph build ----------------
__global__ void k_detect(const long long* __restrict__ p) {
    if (threadIdx.x == 0) {
        int f = 0;
        for (int i = 0; i < 16; i++) { long long v = p[i]; if (v < 0 || v >= NN) f = 1; }
        g_i32 = f;
    }
}

__global__ void k_zero() {
    int i = blockIdx.x * blockDim.x + threadIdx.x;
    if (i < NN) { g_count[i] = 0; g_cursor[i] = 0; }
}

__global__ void k_count(const void* __restrict__ ei) {
    int e = blockIdx.x * blockDim.x + threadIdx.x;
    if (e >= EE) return;
    int dst = g_i32 ? ((const int*)ei)[EE + e] : (int)((const long long*)ei)[EE + e];
    atomicAdd(&g_count[dst], 1);
}

__global__ void k_scan() {
    __shared__ int sums[1024];
    int t = threadIdx.x;
    int base = t * 8;
    int loc[8]; int s = 0;
#pragma unroll
    for (int q = 0; q < 8; q++) { loc[q] = s; s += g_count[base + q]; }
    sums[t] = s;
    __syncthreads();
    for (int off = 1; off < 1024; off <<= 1) {
        int v = (t >= off) ? sums[t - off] : 0;
        __syncthreads();
        sums[t] += v;
        __syncthreads();
    }
    int ex = sums[t] - s;
#pragma unroll
    for (int q = 0; q < 8; q++) g_row[base + q] = ex + loc[q];
    if (t == 1023) g_row[NN] = ex + s;
    for (int i = t; i < NN; i += 1024)
        g_dinv[i] = rsqrtf((float)(g_count[i] + 1));
}

__global__ void k_fill(const void* __restrict__ ei) {
    int e = blockIdx.x * blockDim.x + threadIdx.x;
    if (e >= EE) return;
    int src, dst;
    if (g_i32) { const int* q = (const int*)ei; src = q[e]; dst = q[EE + e]; }
    else { const long long* q = (const long long*)ei; src = (int)q[e]; dst = (int)q[EE + e]; }
    int pos = atomicAdd(&g_cursor[dst], 1);
    g_csr[g_row[dst] + pos] = src;
}

// ---------------- feature scaling: g_xs = x * dinv[node] ----------------
__global__ void k_scalex(const float* __restrict__ x) {
    int idx = blockIdx.x * blockDim.x + threadIdx.x;   // N*128 threads
    g_xs[idx] = x[idx] * g_dinv[idx >> 7];
}

// ---------------- gather aggregation ----------------
// g_agg[i] = dinv[i] * (sum_{src in N(i)} ins[src] + ins[i]); ins pre-scaled by dinv[src]
template <int C, int SRC>
__global__ void k_gather() {
    const float* ins = (SRC == 0) ? g_xs : g_hs;
    int i = blockIdx.x;
    int f = threadIdx.x;
    float acc = __ldg(&ins[i * C + f]);       // self loop (already scaled)
    int e = g_row[i], end = g_row[i + 1];
    for (; e + 4 <= end; e += 4) {
        int s0 = g_csr[e], s1 = g_csr[e + 1], s2 = g_csr[e + 2], s3 = g_csr[e + 3];
        float v0 = __ldg(&ins[s0 * C + f]);
        float v1 = __ldg(&ins[s1 * C + f]);
        float v2 = __ldg(&ins[s2 * C + f]);
        float v3 = __ldg(&ins[s3 * C + f]);
        acc += v0; acc += v1; acc += v2; acc += v3;
    }
    for (; e < end; ++e) acc += __ldg(&ins[g_csr[e] * C + f]);
    g_agg[i * C + f] = acc * g_dinv[i];
}

// ---------------- GEMM: g_h = relu(g_agg @ W^T + bias), g_hs = g_h * dinv ----------------
// g_agg: [NN, K] row-major, W: [HD, K] row-major
#define BM 64
#define BN 64
#define BK 16

template <int K>
__global__ void __launch_bounds__(256) k_gemm(
    const float* __restrict__ W, const float* __restrict__ bias)
{
    __shared__ __align__(16) float As[BK][BM + 4];
    __shared__ __align__(16) float Bs[BK][BN + 4];
    int tid = threadIdx.x;
    int bm = blockIdx.x * BM, bn = blockIdx.y * BN;
    int lr = tid >> 2;               // 0..63
    int lc = (tid & 3) * 4;          // 0,4,8,12
    int tr = tid >> 4;               // 0..15
    int tc = tid & 15;               // 0..15

    u64 acc[4][2];
#pragma unroll
    for (int i = 0; i < 4; i++) { acc[i][0] = 0ull; acc[i][1] = 0ull; }

    for (int k0 = 0; k0 < K; k0 += BK) {
        __syncthreads();
        float4 va = *(const float4*)&g_agg[(size_t)(bm + lr) * K + k0 + lc];
        float4 vb = *(const float4*)&W[(size_t)(bn + lr) * K + k0 + lc];
        As[lc + 0][lr] = va.x; As[lc + 1][lr] = va.y; As[lc + 2][lr] = va.z; As[lc + 3][lr] = va.w;
        Bs[lc + 0][lr] = vb.x; Bs[lc + 1][lr] = vb.y; Bs[lc + 2][lr] = vb.z; Bs[lc + 3][lr] = vb.w;
        __syncthreads();
#pragma unroll
        for (int kk = 0; kk < BK; kk++) {
            float4 av = *(const float4*)&As[kk][tr * 4];
            ulonglong2 bv = *(const ulonglong2*)&Bs[kk][tc * 4];
            u64 a2;
            a2 = pk2(av.x, av.x); fma2(acc[0][0], a2, bv.x); fma2(acc[0][1], a2, bv.y);
            a2 = pk2(av.y, av.y); fma2(acc[1][0], a2, bv.x); fma2(acc[1][1], a2, bv.y);
            a2 = pk2(av.z, av.z); fma2(acc[2][0], a2, bv.x); fma2(acc[2][1], a2, bv.y);
            a2 = pk2(av.w, av.w); fma2(acc[3][0], a2, bv.x); fma2(acc[3][1], a2, bv.y);
        }
    }

    float4 bb = *(const float4*)&bias[bn + tc * 4];
#pragma unroll
    for (int ii = 0; ii < 4; ii++) {
        int row = bm + tr * 4 + ii;
        float2 p0 = up2(acc[ii][0]);
        float2 p1 = up2(acc[ii][1]);
        float c0 = fmaxf(p0.x + bb.x, 0.f);
        float c1 = fmaxf(p0.y + bb.y, 0.f);
        float c2 = fmaxf(p1.x + bb.z, 0.f);
        float c3 = fmaxf(p1.y + bb.w, 0.f);
        size_t o = (size_t)row * HD + bn + tc * 4;
        *(float4*)&g_h[o] = make_float4(c0, c1, c2, c3);
        float dv = g_dinv[row];
        *(float4*)&g_hs[o] = make_float4(c0 * dv, c1 * dv, c2 * dv, c3 * dv);
    }
}

// ---------------- fold out_W into u,v vectors ----------------
__global__ void k_uv(const float* __restrict__ oW, const float* __restrict__ ob,
                     const float* __restrict__ eW, const float* __restrict__ eb) {
    int k = threadIdx.x;
    float u = 0.f, v = 0.f;
    for (int j = 0; j < HD; j++) {
        float w = oW[j * HD + k];
        u = fmaf(w, eW[j], u);
        v = fmaf(w, eW[HD + j], v);
    }
    g_u[k] = u; g_v[k] = v;
    if (k == 0) {
        float s = 0.f;
        for (int j = 0; j < HD; j++) s = fmaf(ob[j], eW[j], s);
        g_ca = s;
    }
    if (k == 1) {
        float s = 0.f;
        for (int j = 0; j < HD; j++) s = fmaf(ob[j], eW[HD + j], s);
        g_cb = s + eb[0];
    }
}

// ---------------- per-node dots: a[i] = h3[i].u + ca ; b[i] = h3[i].v + cb ----------------
__global__ void k_dots() {
    int node = blockIdx.x * 8 + (threadIdx.x >> 5);
    int lane = threadIdx.x & 31;
    const float* hp = g_h + (size_t)node * HD;
    float s1 = 0.f, s2 = 0.f;
#pragma unroll
    for (int t = 0; t < 8; t++) {
        int f = lane + 32 * t;
        float hv = hp[f];
        s1 = fmaf(hv, g_u[f], s1);
        s2 = fmaf(hv, g_v[f], s2);
    }
#pragma unroll
    for (int o = 16; o; o >>= 1) {
        s1 += __shfl_xor_sync(0xFFFFFFFFu, s1, o);
        s2 += __shfl_xor_sync(0xFFFFFFFFu, s2, o);
    }
    if (lane == 0) { g_a[node] = s1 + g_ca; g_b[node] = s2 + g_cb; }
}

// ---------------- rank-2 broadcast into the 8192x8192 output ----------------
// grid: (2, NN), 256 threads; each thread writes 4 float4 (64B) strided.
__global__ void k_logits(float* __restrict__ out) {
    int i = blockIdx.y;
    float ai = g_a[i];
    int base = blockIdx.x * 1024 + threadIdx.x;       // float4 index
    float4* orow = (float4*)out + (size_t)i * (NN / 4);
    const float4* bp = (const float4*)g_b;
#pragma unroll
    for (int q = 0; q < 4; q++) {
        int c4 = base + q * 256;
        float4 bv = bp[c4];
        orow[c4] = make_float4(ai + bv.x, ai + bv.y, ai + bv.z, ai + bv.w);
    }
}

// ---------------- launch ----------------
extern "C" void kernel_launch(void* const* d_in, const int* in_sizes, int n_in,
                              void* d_out, int out_size) {
    const float* x   = (const float*)d_in[0];
    const void*  ei  = d_in[1];
    const float* W0  = (const float*)d_in[2];
    const float* b0  = (const float*)d_in[3];
    const float* W1  = (const float*)d_in[4];
    const float* b1  = (const float*)d_in[5];
    const float* W2  = (const float*)d_in[6];
    const float* b2  = (const float*)d_in[7];
    const float* oW  = (const float*)d_in[8];
    const float* ob  = (const float*)d_in[9];
    const float* eW  = (const float*)d_in[10];
    const float* eb  = (const float*)d_in[11];
    float* out = (float*)d_out;

    // graph build
    k_detect<<<1, 32>>>((const long long*)ei);
    k_zero<<<NN / 256, 256>>>();
    k_count<<<EE / 256, 256>>>(ei);
    k_scan<<<1, 1024>>>();
    k_fill<<<EE / 256, 256>>>(ei);

    // scale x by dinv
    k_scalex<<<NN * IND / 256, 256>>>(x);

    // layer 0: aggregate (128 cols) then GEMM K=128
    k_gather<IND, 0><<<NN, IND>>>();
    k_gemm<IND><<<dim3(NN / BM, HD / BN), 256>>>(W0, b0);

    // layer 1
    k_gather<HD, 1><<<NN, HD>>>();
    k_gemm<HD><<<dim3(NN / BM, HD / BN), 256>>>(W1, b1);

    // layer 2
    k_gather<HD, 1><<<NN, HD>>>();
    k_gemm<HD><<<dim3(NN / BM, HD / BN), 256>>>(W2, b2);

    // fold out linear into u,v and compute per-node dots
    k_uv<<<1, HD>>>(oW, ob, eW, eb);
    k_dots<<<NN / 8, 256>>>();

    // rank-2 broadcast output
    k_logits<<<dim3(2, NN), 256>>>(out);
}

// round 4
// speedup vs baseline: 1.0883x; 1.0883x over previous
#include <cuda_runtime.h>
#include <cuda_fp16.h>
#include <cstdint>

#define NN 8192
#define EE 262144
#define IND 128
#define HD 256

// ---------------- scratch (static device globals; referenced ONLY in device code) ----------------
__device__ int   g_count[NN];
__device__ int   g_cursor[NN];
__device__ __align__(16) int g_row[NN + 8];
__device__ int   g_csr[EE];
__device__ float g_dinv[NN];
__device__ float g_xs[NN * IND];      // scaled input features (fp32)
__device__ float g_agg[NN * HD];      // aggregation output (fp32)
__device__ float g_h[NN * HD];        // layer output (relu, fp32)
__device__ __half g_hsh[NN * HD];     // layer output * dinv, fp16 (gather input)
__device__ float g_u[HD], g_v[HD];
__device__ float g_a[NN], g_b[NN];
__device__ float g_ca, g_cb;
__device__ int   g_i32;               // edge_index dtype flag

// ---------------- f32x2 helpers ----------------
typedef unsigned long long u64;

__device__ __forceinline__ u64 pk2(float x, float y) {
    u64 r; asm("mov.b64 %0, {%1,%2};" : "=l"(r) : "f"(x), "f"(y)); return r;
}
__device__ __forceinline__ void fma2(u64 &d, u64 a, u64 b) {
    asm("fma.rn.f32x2 %0, %1, %2, %0;" : "+l"(d) : "l"(a), "l"(b));
}
__device__ __forceinline__ float2 up2(u64 v) {
    float2 r; asm("mov.b64 {%0,%1}, %2;" : "=f"(r.x), "=f"(r.y) : "l"(v)); return r;
}

// ---------------- graph build ----------------
__global__ void k_detect(const long long* __restrict__ p) {
    if (threadIdx.x == 0) {
        int f = 0;
        for (int i = 0; i < 16; i++) { long long v = p[i]; if (v < 0 || v >= NN) f = 1; }
        g_i32 = f;
    }
}

__global__ void k_zero() {
    int i = blockIdx.x * blockDim.x + threadIdx.x;
    if (i < NN) { g_count[i] = 0; g_cursor[i] = 0; }
}

__global__ void k_count(const void* __restrict__ ei) {
    int e = blockIdx.x * blockDim.x + threadIdx.x;
    if (e >= EE) return;
    int dst = g_i32 ? ((const int*)ei)[EE + e] : (int)((const long long*)ei)[EE + e];
    atomicAdd(&g_count[dst], 1);
}

// warp-shuffle scan: 1024 threads, 8 counts each; 2 barriers total
__global__ void k_scan() {
    __shared__ int wsum[32];
    int t = threadIdx.x;
    int lane = t & 31, w = t >> 5;
    int4 c0 = *(const int4*)&g_count[t * 8];
    int4 c1 = *(const int4*)&g_count[t * 8 + 4];
    int cc[8] = {c0.x, c0.y, c0.z, c0.w, c1.x, c1.y, c1.z, c1.w};
    int loc[8]; int s = 0;
#pragma unroll
    for (int q = 0; q < 8; q++) { loc[q] = s; s += cc[q]; }
    // inclusive warp scan of s
    int p = s;
#pragma unroll
    for (int off = 1; off < 32; off <<= 1) {
        int n = __shfl_up_sync(0xFFFFFFFFu, p, off);
        if (lane >= off) p += n;
    }
    if (lane == 31) wsum[w] = p;
    __syncthreads();
    if (w == 0) {
        int v = wsum[lane];
#pragma unroll
        for (int off = 1; off < 32; off <<= 1) {
            int n = __shfl_up_sync(0xFFFFFFFFu, v, off);
            if (lane >= off) v += n;
        }
        wsum[lane] = v;
    }
    __syncthreads();
    int base = (w ? wsum[w - 1] : 0) + p - s;   // exclusive prefix for this thread
    int4 r0 = make_int4(base + loc[0], base + loc[1], base + loc[2], base + loc[3]);
    int4 r1 = make_int4(base + loc[4], base + loc[5], base + loc[6], base + loc[7]);
    *(int4*)&g_row[t * 8] = r0;
    *(int4*)&g_row[t * 8 + 4] = r1;
    if (t == 1023) g_row[NN] = base + s;
#pragma unroll
    for (int q = 0; q < 8; q++)
        g_dinv[t * 8 + q] = rsqrtf((float)(cc[q] + 1));
}

__global__ void k_fill(const void* __restrict__ ei) {
    int e = blockIdx.x * blockDim.x + threadIdx.x;
    if (e >= EE) return;
    int src, dst;
    if (g_i32) { const int* q = (const int*)ei; src = q[e]; dst = q[EE + e]; }
    else { const long long* q = (const long long*)ei; src = (int)q[e]; dst = (int)q[EE + e]; }
    int pos = atomicAdd(&g_cursor[dst], 1);
    g_csr[g_row[dst] + pos] = src;
}

// ---------------- feature scaling: g_xs = x * dinv[node] (fp32) ----------------
__global__ void k_scalex(const float* __restrict__ x) {
    int idx = blockIdx.x * blockDim.x + threadIdx.x;   // N*128 threads
    g_xs[idx] = x[idx] * g_dinv[idx >> 7];
}

// ---------------- gather fp32 (layer 0, C=128) ----------------
__global__ void k_gather_f() {
    const float* ins = g_xs;
    int i = blockIdx.x;
    int f = threadIdx.x;
    float acc = __ldg(&ins[i * IND + f]);     // self loop (already scaled)
    int e = g_row[i], end = g_row[i + 1];
    for (; e + 4 <= end; e += 4) {
        int s0 = g_csr[e], s1 = g_csr[e + 1], s2 = g_csr[e + 2], s3 = g_csr[e + 3];
        acc += __ldg(&ins[s0 * IND + f]);
        acc += __ldg(&ins[s1 * IND + f]);
        acc += __ldg(&ins[s2 * IND + f]);
        acc += __ldg(&ins[s3 * IND + f]);
    }
    for (; e < end; ++e) acc += __ldg(&ins[g_csr[e] * IND + f]);
    g_agg[i * IND + f] = acc * g_dinv[i];
}

// ---------------- gather fp16 (layers 1-2, C=256): 128 threads, half2 per thread ----------------
__global__ void k_gather_h() {
    const __half2* ins = (const __half2*)g_hsh;
    int i = blockIdx.x;
    int t = threadIdx.x;                       // 0..127 (half2 col)
    float2 acc = __half22float2(__ldg(&ins[i * 128 + t]));   // self loop
    int e = g_row[i], end = g_row[i + 1];
    for (; e + 4 <= end; e += 4) {
        int s0 = g_csr[e], s1 = g_csr[e + 1], s2 = g_csr[e + 2], s3 = g_csr[e + 3];
        float2 v0 = __half22float2(__ldg(&ins[s0 * 128 + t]));
        float2 v1 = __half22float2(__ldg(&ins[s1 * 128 + t]));
        float2 v2 = __half22float2(__ldg(&ins[s2 * 128 + t]));
        float2 v3 = __half22float2(__ldg(&ins[s3 * 128 + t]));
        acc.x += v0.x + v1.x + v2.x + v3.x;
        acc.y += v0.y + v1.y + v2.y + v3.y;
    }
    for (; e < end; ++e) {
        float2 v = __half22float2(__ldg(&ins[g_csr[e] * 128 + t]));
        acc.x += v.x; acc.y += v.y;
    }
    float dv = g_dinv[i];
    ((float2*)g_agg)[i * 128 + t] = make_float2(acc.x * dv, acc.y * dv);
}

// ---------------- GEMM: g_h = relu(g_agg @ W^T + bias), g_hsh = half(g_h * dinv) ----------------
// g_agg: [NN, K] row-major, W: [HD, K] row-major. 128x128 tile, 8x8 per thread.
#define BM 128
#define BN 128
#define BK 16

template <int K>
__global__ void __launch_bounds__(256) k_gemm(
    const float* __restrict__ W, const float* __restrict__ bias)
{
    __shared__ __align__(16) float As[BK][BM + 4];
    __shared__ __align__(16) float Bs[BK][BN + 4];
    int tid = threadIdx.x;
    int bm = blockIdx.x * BM, bn = blockIdx.y * BN;
    int lr = tid >> 1;                 // 0..127 (tile row for loads)
    int lc = (tid & 1) * 8;            // 0 or 8
    int tr = tid >> 4;                 // 0..15 (8-row group)
    int tc = tid & 15;                 // 0..15 (8-col group)

    u64 acc[8][4];
#pragma unroll
    for (int r = 0; r < 8; r++)
#pragma unroll
        for (int c = 0; c < 4; c++) acc[r][c] = 0ull;

    for (int k0 = 0; k0 < K; k0 += BK) {
        __syncthreads();
        float4 va0 = *(const float4*)&g_agg[(size_t)(bm + lr) * K + k0 + lc];
        float4 va1 = *(const float4*)&g_agg[(size_t)(bm + lr) * K + k0 + lc + 4];
        float4 vb0 = *(const float4*)&W[(size_t)(bn + lr) * K + k0 + lc];
        float4 vb1 = *(const float4*)&W[(size_t)(bn + lr) * K + k0 + lc + 4];
        As[lc + 0][lr] = va0.x; As[lc + 1][lr] = va0.y; As[lc + 2][lr] = va0.z; As[lc + 3][lr] = va0.w;
        As[lc + 4][lr] = va1.x; As[lc + 5][lr] = va1.y; As[lc + 6][lr] = va1.z; As[lc + 7][lr] = va1.w;
        Bs[lc + 0][lr] = vb0.x; Bs[lc + 1][lr] = vb0.y; Bs[lc + 2][lr] = vb0.z; Bs[lc + 3][lr] = vb0.w;
        Bs[lc + 4][lr] = vb1.x; Bs[lc + 5][lr] = vb1.y; Bs[lc + 6][lr] = vb1.z; Bs[lc + 7][lr] = vb1.w;
        __syncthreads();
#pragma unroll
        for (int kk = 0; kk < BK; kk++) {
            float4 a0 = *(const float4*)&As[kk][tr * 8];
            float4 a1 = *(const float4*)&As[kk][tr * 8 + 4];
            ulonglong2 b0 = *(const ulonglong2*)&Bs[kk][tc * 8];
            ulonglong2 b1 = *(const ulonglong2*)&Bs[kk][tc * 8 + 4];
            u64 aa;
            aa = pk2(a0.x, a0.x); fma2(acc[0][0], aa, b0.x); fma2(acc[0][1], aa, b0.y); fma2(acc[0][2], aa, b1.x); fma2(acc[0][3], aa, b1.y);
            aa = pk2(a0.y, a0.y); fma2(acc[1][0], aa, b0.x); fma2(acc[1][1], aa, b0.y); fma2(acc[1][2], aa, b1.x); fma2(acc[1][3], aa, b1.y);
            aa = pk2(a0.z, a0.z); fma2(acc[2][0], aa, b0.x); fma2(acc[2][1], aa, b0.y); fma2(acc[2][2], aa, b1.x); fma2(acc[2][3], aa, b1.y);
            aa = pk2(a0.w, a0.w); fma2(acc[3][0], aa, b0.x); fma2(acc[3][1], aa, b0.y); fma2(acc[3][2], aa, b1.x); fma2(acc[3][3], aa, b1.y);
            aa = pk2(a1.x, a1.x); fma2(acc[4][0], aa, b0.x); fma2(acc[4][1], aa, b0.y); fma2(acc[4][2], aa, b1.x); fma2(acc[4][3], aa, b1.y);
            aa = pk2(a1.y, a1.y); fma2(acc[5][0], aa, b0.x); fma2(acc[5][1], aa, b0.y); fma2(acc[5][2], aa, b1.x); fma2(acc[5][3], aa, b1.y);
            aa = pk2(a1.z, a1.z); fma2(acc[6][0], aa, b0.x); fma2(acc[6][1], aa, b0.y); fma2(acc[6][2], aa, b1.x); fma2(acc[6][3], aa, b1.y);
            aa = pk2(a1.w, a1.w); fma2(acc[7][0], aa, b0.x); fma2(acc[7][1], aa, b0.y); fma2(acc[7][2], aa, b1.x); fma2(acc[7][3], aa, b1.y);
        }
    }

    float4 bb0 = *(const float4*)&bias[bn + tc * 8];
    float4 bb1 = *(const float4*)&bias[bn + tc * 8 + 4];
#pragma unroll
    for (int r = 0; r < 8; r++) {
        int row = bm + tr * 8 + r;
        float2 p0 = up2(acc[r][0]);
        float2 p1 = up2(acc[r][1]);
        float2 p2 = up2(acc[r][2]);
        float2 p3 = up2(acc[r][3]);
        float c0 = fmaxf(p0.x + bb0.x, 0.f);
        float c1 = fmaxf(p0.y + bb0.y, 0.f);
        float c2 = fmaxf(p1.x + bb0.z, 0.f);
        float c3 = fmaxf(p1.y + bb0.w, 0.f);
        float c4 = fmaxf(p2.x + bb1.x, 0.f);
        float c5 = fmaxf(p2.y + bb1.y, 0.f);
        float c6 = fmaxf(p3.x + bb1.z, 0.f);
        float c7 = fmaxf(p3.y + bb1.w, 0.f);
        size_t o = (size_t)row * HD + bn + tc * 8;
        *(float4*)&g_h[o]     = make_float4(c0, c1, c2, c3);
        *(float4*)&g_h[o + 4] = make_float4(c4, c5, c6, c7);
        float dv = g_dinv[row];
        __half2 h0 = __floats2half2_rn(c0 * dv, c1 * dv);
        __half2 h1 = __floats2half2_rn(c2 * dv, c3 * dv);
        __half2 h2 = __floats2half2_rn(c4 * dv, c5 * dv);
        __half2 h3 = __floats2half2_rn(c6 * dv, c7 * dv);
        uint4 hp;
        hp.x = *(unsigned int*)&h0; hp.y = *(unsigned int*)&h1;
        hp.z = *(unsigned int*)&h2; hp.w = *(unsigned int*)&h3;
        *(uint4*)&g_hsh[o] = hp;
    }
}

// ---------------- fold out_W into u,v vectors ----------------
__global__ void k_uv(const float* __restrict__ oW, const float* __restrict__ ob,
                     const float* __restrict__ eW, const float* __restrict__ eb) {
    int k = threadIdx.x;
    float u = 0.f, v = 0.f;
    for (int j = 0; j < HD; j++) {
        float w = oW[j * HD + k];
        u = fmaf(w, eW[j], u);
        v = fmaf(w, eW[HD + j], v);
    }
    g_u[k] = u; g_v[k] = v;
    if (k == 0) {
        float s = 0.f;
        for (int j = 0; j < HD; j++) s = fmaf(ob[j], eW[j], s);
        g_ca = s;
    }
    if (k == 1) {
        float s = 0.f;
        for (int j = 0; j < HD; j++) s = fmaf(ob[j], eW[HD + j], s);
        g_cb = s + eb[0];
    }
}

// ---------------- per-node dots ----------------
__global__ void k_dots() {
    int node = blockIdx.x * 8 + (threadIdx.x >> 5);
    int lane = threadIdx.x & 31;
    const float* hp = g_h + (size_t)node * HD;
    float s1 = 0.f, s2 = 0.f;
#pragma unroll
    for (int t = 0; t < 8; t++) {
        int f = lane + 32 * t;
        float hv = hp[f];
        s1 = fmaf(hv, g_u[f], s1);
        s2 = fmaf(hv, g_v[f], s2);
    }
#pragma unroll
    for (int o = 16; o; o >>= 1) {
        s1 += __shfl_xor_sync(0xFFFFFFFFu, s1, o);
        s2 += __shfl_xor_sync(0xFFFFFFFFu, s2, o);
    }
    if (lane == 0) { g_a[node] = s1 + g_ca; g_b[node] = s2 + g_cb; }
}

// ---------------- rank-2 broadcast into the 8192x8192 output ----------------
__global__ void k_logits(float* __restrict__ out) {
    int i = blockIdx.y;
    float ai = g_a[i];
    int base = blockIdx.x * 1024 + threadIdx.x;       // float4 index
    float4* orow = (float4*)out + (size_t)i * (NN / 4);
    const float4* bp = (const float4*)g_b;
#pragma unroll
    for (int q = 0; q < 4; q++) {
        int c4 = base + q * 256;
        float4 bv = bp[c4];
        orow[c4] = make_float4(ai + bv.x, ai + bv.y, ai + bv.z, ai + bv.w);
    }
}

// ---------------- launch ----------------
extern "C" void kernel_launch(void* const* d_in, const int* in_sizes, int n_in,
                              void* d_out, int out_size) {
    const float* x   = (const float*)d_in[0];
    const void*  ei  = d_in[1];
    const float* W0  = (const float*)d_in[2];
    const float* b0  = (const float*)d_in[3];
    const float* W1  = (const float*)d_in[4];
    const float* b1  = (const float*)d_in[5];
    const float* W2  = (const float*)d_in[6];
    const float* b2  = (const float*)d_in[7];
    const float* oW  = (const float*)d_in[8];
    const float* ob  = (const float*)d_in[9];
    const float* eW  = (const float*)d_in[10];
    const float* eb  = (const float*)d_in[11];
    float* out = (float*)d_out;

    // graph build
    k_detect<<<1, 32>>>((const long long*)ei);
    k_zero<<<NN / 256, 256>>>();
    k_count<<<EE / 256, 256>>>(ei);
    k_scan<<<1, 1024>>>();
    k_fill<<<EE / 256, 256>>>(ei);

    // scale x by dinv
    k_scalex<<<NN * IND / 256, 256>>>(x);

    // layer 0: aggregate (fp32, 128 cols) then GEMM K=128
    k_gather_f<<<NN, IND>>>();
    k_gemm<IND><<<dim3(NN / BM, HD / BN), 256>>>(W0, b0);

    // layer 1 (fp16 gather)
    k_gather_h<<<NN, 128>>>();
    k_gemm<HD><<<dim3(NN / BM, HD / BN), 256>>>(W1, b1);

    // layer 2 (fp16 gather)
    k_gather_h<<<NN, 128>>>();
    k_gemm<HD><<<dim3(NN / BM, HD / BN), 256>>>(W2, b2);

    // fold out linear into u,v and compute per-node dots
    k_uv<<<1, HD>>>(oW, ob, eW, eb);
    k_dots<<<NN / 8, 256>>>();

    // rank-2 broadcast output
    k_logits<<<dim3(2, NN), 256>>>(out);
}

// round 8
// speedup vs baseline: 1.3958x; 1.2826x over previous
#include <cuda_runtime.h>
#include <cuda_fp16.h>
#include <cstdint>

#define NN 8192
#define EE 262144
#define IND 128
#define HD 256

// ---------------- scratch (static device globals; referenced ONLY in device code) ----------------
__device__ int    g_count[NN];
__device__ int    g_cursor[NN];
__device__ __align__(16) int g_row[NN + 8];
__device__ int    g_csr[EE];
__device__ float  g_dinv[NN];
__device__ __align__(16) __half g_xsh[NN * IND];   // scaled input features fp16
__device__ __align__(16) __half g_aggh[NN * HD];   // aggregation output fp16 (GEMM A)
__device__ __align__(16) __half g_hsh[NN * HD];    // relu(h)*dinv fp16 (gather input / dots input)
__device__ float  g_u[HD], g_v[HD];
__device__ float  g_a[NN], g_b[NN];
__device__ float  g_ca, g_cb;
__device__ int    g_i32;

__device__ __forceinline__ uint32_t smem_u32(const void* p) {
    uint32_t a;
    asm("{ .reg .u64 t; cvta.to.shared.u64 t, %1; cvt.u32.u64 %0, t; }" : "=r"(a) : "l"(p));
    return a;
}
__device__ __forceinline__ void ldsm4(uint32_t& r0, uint32_t& r1, uint32_t& r2, uint32_t& r3, uint32_t addr) {
    asm volatile("ldmatrix.sync.aligned.m8n8.x4.shared.b16 {%0,%1,%2,%3}, [%4];"
                 : "=r"(r0), "=r"(r1), "=r"(r2), "=r"(r3) : "r"(addr));
}
__device__ __forceinline__ void mma16816(float* c, uint32_t a0, uint32_t a1, uint32_t a2, uint32_t a3,
                                         uint32_t b0, uint32_t b1) {
    asm volatile("mma.sync.aligned.m16n8k16.row.col.f32.f16.f16.f32 "
                 "{%0,%1,%2,%3}, {%4,%5,%6,%7}, {%8,%9}, {%0,%1,%2,%3};"
                 : "+f"(c[0]), "+f"(c[1]), "+f"(c[2]), "+f"(c[3])
                 : "r"(a0), "r"(a1), "r"(a2), "r"(a3), "r"(b0), "r"(b1));
}

// ---------------- graph build ----------------
__global__ void k_init(const long long* __restrict__ p) {
    int i = blockIdx.x * blockDim.x + threadIdx.x;
    g_count[i] = 0; g_cursor[i] = 0;
    if (i == 0) {
        int f = 0;
        for (int q = 0; q < 16; q++) { long long v = p[q]; if (v < 0 || v >= NN) f = 1; }
        g_i32 = f;
    }
}

__global__ void k_count(const void* __restrict__ ei) {
    int e = blockIdx.x * blockDim.x + threadIdx.x;
    int dst = g_i32 ? ((const int*)ei)[EE + e] : (int)((const long long*)ei)[EE + e];
    atomicAdd(&g_count[dst], 1);
}

__global__ void k_scan() {
    __shared__ int wsum[32];
    int t = threadIdx.x;
    int lane = t & 31, w = t >> 5;
    int4 c0 = *(const int4*)&g_count[t * 8];
    int4 c1 = *(const int4*)&g_count[t * 8 + 4];
    int cc[8] = {c0.x, c0.y, c0.z, c0.w, c1.x, c1.y, c1.z, c1.w};
    int loc[8]; int s = 0;
#pragma unroll
    for (int q = 0; q < 8; q++) { loc[q] = s; s += cc[q]; }
    int p = s;
#pragma unroll
    for (int off = 1; off < 32; off <<= 1) {
        int n = __shfl_up_sync(0xFFFFFFFFu, p, off);
        if (lane >= off) p += n;
    }
    if (lane == 31) wsum[w] = p;
    __syncthreads();
    if (w == 0) {
        int v = wsum[lane];
#pragma unroll
        for (int off = 1; off < 32; off <<= 1) {
            int n = __shfl_up_sync(0xFFFFFFFFu, v, off);
            if (lane >= off) v += n;
        }
        wsum[lane] = v;
    }
    __syncthreads();
    int base = (w ? wsum[w - 1] : 0) + p - s;
    *(int4*)&g_row[t * 8]     = make_int4(base + loc[0], base + loc[1], base + loc[2], base + loc[3]);
    *(int4*)&g_row[t * 8 + 4] = make_int4(base + loc[4], base + loc[5], base + loc[6], base + loc[7]);
    if (t == 1023) g_row[NN] = base + s;
#pragma unroll
    for (int q = 0; q < 8; q++)
        g_dinv[t * 8 + q] = rsqrtf((float)(cc[q] + 1));
}

__global__ void k_fill(const void* __restrict__ ei) {
    int e = blockIdx.x * blockDim.x + threadIdx.x;
    int src, dst;
    if (g_i32) { const int* q = (const int*)ei; src = q[e]; dst = q[EE + e]; }
    else { const long long* q = (const long long*)ei; src = (int)q[e]; dst = (int)q[EE + e]; }
    int pos = atomicAdd(&g_cursor[dst], 1);
    g_csr[g_row[dst] + pos] = src;
}

// ---------------- scale x by dinv -> fp16 ----------------
__global__ void k_scalex(const float* __restrict__ x) {
    int idx = blockIdx.x * blockDim.x + threadIdx.x;   // NN*64 half2 slots
    float2 v = ((const float2*)x)[idx];
    float dv = g_dinv[idx >> 6];
    ((__half2*)g_xsh)[idx] = __floats2half2_rn(v.x * dv, v.y * dv);
}

// ---------------- gather (fp16 in, fp16 out) ----------------
template <int CH, int SRC>
__global__ void k_gather() {
    const __half2* ins = (const __half2*)(SRC == 0 ? g_xsh : g_hsh);
    int i = blockIdx.x;
    int t = threadIdx.x;
    float2 acc = __half22float2(__ldg(&ins[i * CH + t]));    // self loop
    int e = g_row[i], end = g_row[i + 1];
    for (; e + 4 <= end; e += 4) {
        int s0 = g_csr[e], s1 = g_csr[e + 1], s2 = g_csr[e + 2], s3 = g_csr[e + 3];
        float2 v0 = __half22float2(__ldg(&ins[s0 * CH + t]));
        float2 v1 = __half22float2(__ldg(&ins[s1 * CH + t]));
        float2 v2 = __half22float2(__ldg(&ins[s2 * CH + t]));
        float2 v3 = __half22float2(__ldg(&ins[s3 * CH + t]));
        acc.x += v0.x + v1.x + v2.x + v3.x;
        acc.y += v0.y + v1.y + v2.y + v3.y;
    }
    for (; e < end; ++e) {
        float2 v = __half22float2(__ldg(&ins[g_csr[e] * CH + t]));
        acc.x += v.x; acc.y += v.y;
    }
    float dv = g_dinv[i];
    ((__half2*)g_aggh)[i * CH + t] = __floats2half2_rn(acc.x * dv, acc.y * dv);
}

// ---------------- HMMA GEMM: g_hsh = fp16(relu(g_aggh @ W^T + bias) * dinv) ----------------
// CTA tile 128(M) x 128(N), full K in SMEM (padded rows, K+8 halves).
// 8 warps: warp_m = wid&3 (32 rows), warp_n = wid>>2 (64 cols).
template <int K>
__global__ void __launch_bounds__(256) k_gemm(const float* __restrict__ W, const float* __restrict__ bias) {
    extern __shared__ __half smh[];
    const int LDR = K + 8;                       // halves per row
    __half* As = smh;                            // [128][LDR]
    __half* Bs = smh + 128 * LDR;                // [128][LDR]
    int tid = threadIdx.x;
    int wid = tid >> 5, lane = tid & 31;
    int bm = blockIdx.x * 128;
    int bn = blockIdx.y * 128;

    // load A tile (fp16 copy)
    for (int idx = tid; idx < 128 * (K / 8); idx += 256) {
        int row = idx / (K / 8);
        int col = (idx % (K / 8)) * 8;
        uint4 v = *(const uint4*)&g_aggh[(size_t)(bm + row) * K + col];
        *(uint4*)&As[row * LDR + col] = v;
    }
    // load B tile (W rows bn..bn+127, fp32 -> fp16)
    for (int idx = tid; idx < 128 * (K / 8); idx += 256) {
        int row = idx / (K / 8);
        int col = (idx % (K / 8)) * 8;
        float4 f0 = *(const float4*)&W[(size_t)(bn + row) * K + col];
        float4 f1 = *(const float4*)&W[(size_t)(bn + row) * K + col + 4];
        __half2 h0 = __floats2half2_rn(f0.x, f0.y);
        __half2 h1 = __floats2half2_rn(f0.z, f0.w);
        __half2 h2 = __floats2half2_rn(f1.x, f1.y);
        __half2 h3 = __floats2half2_rn(f1.z, f1.w);
        uint4 hp;
        hp.x = *(uint32_t*)&h0; hp.y = *(uint32_t*)&h1;
        hp.z = *(uint32_t*)&h2; hp.w = *(uint32_t*)&h3;
        *(uint4*)&Bs[row * LDR + col] = hp;
    }
    __syncthreads();

    int wm = (wid & 3) * 32;        // warp M offset in tile
    int wn = (wid >> 2) * 64;       // warp N offset in tile
    int lrow = lane & 15, lcol = lane >> 4;   // ldmatrix addressing

    float acc[2][8][4];
#pragma unroll
    for (int i = 0; i < 2; i++)
#pragma unroll
        for (int j = 0; j < 8; j++)
#pragma unroll
            for (int q = 0; q < 4; q++) acc[i][j][q] = 0.f;

    uint32_t a_base = smem_u32(As);
    uint32_t b_base = smem_u32(Bs);

#pragma unroll 2
    for (int k0 = 0; k0 < K; k0 += 16) {
        uint32_t a[2][4];
#pragma unroll
        for (int mf = 0; mf < 2; mf++) {
            uint32_t addr = a_base + ((wm + mf * 16 + lrow) * LDR + k0 + lcol * 8) * 2;
            ldsm4(a[mf][0], a[mf][1], a[mf][2], a[mf][3], addr);
        }
        uint32_t b[4][4];
#pragma unroll
        for (int ng = 0; ng < 4; ng++) {
            uint32_t addr = b_base + ((wn + ng * 16 + lrow) * LDR + k0 + lcol * 8) * 2;
            ldsm4(b[ng][0], b[ng][1], b[ng][2], b[ng][3], addr);
        }
#pragma unroll
        for (int mf = 0; mf < 2; mf++)
#pragma unroll
            for (int ng = 0; ng < 4; ng++) {
                mma16816(acc[mf][ng * 2],     a[mf][0], a[mf][1], a[mf][2], a[mf][3], b[ng][0], b[ng][2]);
                mma16816(acc[mf][ng * 2 + 1], a[mf][0], a[mf][1], a[mf][2], a[mf][3], b[ng][1], b[ng][3]);
            }
    }

    // epilogue: C frag m16n8 lane map: rows lane>>2 (+8), cols (lane&3)*2 (+1)
    int crow0 = lane >> 2;
    int ccol  = (lane & 3) * 2;
#pragma unroll
    for (int mf = 0; mf < 2; mf++) {
#pragma unroll
        for (int half = 0; half < 2; half++) {
            int row = bm + wm + mf * 16 + crow0 + half * 8;
            float dv = g_dinv[row];
#pragma unroll
            for (int ng = 0; ng < 8; ng++) {
                int col = bn + wn + ng * 8 + ccol;
                float v0 = acc[mf][ng][half * 2 + 0];
                float v1 = acc[mf][ng][half * 2 + 1];
                v0 = fmaxf(v0 + __ldg(&bias[col]), 0.f) * dv;
                v1 = fmaxf(v1 + __ldg(&bias[col + 1]), 0.f) * dv;
                *(__half2*)&g_hsh[(size_t)row * HD + col] = __floats2half2_rn(v0, v1);
            }
        }
    }
}

// ---------------- fold out_W into u,v vectors ----------------
__global__ void k_uv(const float* __restrict__ oW, const float* __restrict__ ob,
                     const float* __restrict__ eW, const float* __restrict__ eb) {
    int k = threadIdx.x;
    float u = 0.f, v = 0.f;
    for (int j = 0; j < HD; j++) {
        float w = oW[j * HD + k];
        u = fmaf(w, eW[j], u);
        v = fmaf(w, eW[HD + j], v);
    }
    g_u[k] = u; g_v[k] = v;
    if (k == 0) {
        float s = 0.f;
        for (int j = 0; j < HD; j++) s = fmaf(ob[j], eW[j], s);
        g_ca = s;
    }
    if (k == 1) {
        float s = 0.f;
        for (int j = 0; j < HD; j++) s = fmaf(ob[j], eW[HD + j], s);
        g_cb = s + eb[0];
    }
}

// ---------------- per-node dots from g_hsh: a[i] = (hs[i].u)/dinv[i] + ca ----------------
__global__ void k_dots() {
    int node = blockIdx.x * 8 + (threadIdx.x >> 5);
    int lane = threadIdx.x & 31;
    const __half2* hp = (const __half2*)g_hsh + (size_t)node * 128;
    float s1 = 0.f, s2 = 0.f;
#pragma unroll
    for (int t = 0; t < 4; t++) {
        int f = lane + 32 * t;
        float2 hv = __half22float2(__ldg(&hp[f]));
        s1 = fmaf(hv.x, g_u[2 * f], fmaf(hv.y, g_u[2 * f + 1], s1));
        s2 = fmaf(hv.x, g_v[2 * f], fmaf(hv.y, g_v[2 * f + 1], s2));
    }
#pragma unroll
    for (int o = 16; o; o >>= 1) {
        s1 += __shfl_xor_sync(0xFFFFFFFFu, s1, o);
        s2 += __shfl_xor_sync(0xFFFFFFFFu, s2, o);
    }
    if (lane == 0) {
        float r = 1.0f / g_dinv[node];
        g_a[node] = s1 * r + g_ca;
        g_b[node] = s2 * r + g_cb;
    }
}

// ---------------- rank-2 broadcast output ----------------
__global__ void k_logits(float* __restrict__ out) {
    int i = blockIdx.y;
    float ai = g_a[i];
    int base = blockIdx.x * 1024 + threadIdx.x;
    float4* orow = (float4*)out + (size_t)i * (NN / 4);
    const float4* bp = (const float4*)g_b;
#pragma unroll
    for (int q = 0; q < 4; q++) {
        int c4 = base + q * 256;
        float4 bv = bp[c4];
        orow[c4] = make_float4(ai + bv.x, ai + bv.y, ai + bv.z, ai + bv.w);
    }
}

// ---------------- launch ----------------
extern "C" void kernel_launch(void* const* d_in, const int* in_sizes, int n_in,
                              void* d_out, int out_size) {
    const float* x   = (const float*)d_in[0];
    const void*  ei  = d_in[1];
    const float* W0  = (const float*)d_in[2];
    const float* b0  = (const float*)d_in[3];
    const float* W1  = (const float*)d_in[4];
    const float* b1  = (const float*)d_in[5];
    const float* W2  = (const float*)d_in[6];
    const float* b2  = (const float*)d_in[7];
    const float* oW  = (const float*)d_in[8];
    const float* ob  = (const float*)d_in[9];
    const float* eW  = (const float*)d_in[10];
    const float* eb  = (const float*)d_in[11];
    float* out = (float*)d_out;

    const int SM128 = 2 * 128 * (128 + 8) * 2;   //  69632 B
    const int SM256 = 2 * 128 * (256 + 8) * 2;   // 135168 B
    cudaFuncSetAttribute(k_gemm<128>, cudaFuncAttributeMaxDynamicSharedMemorySize, SM128);
    cudaFuncSetAttribute(k_gemm<256>, cudaFuncAttributeMaxDynamicSharedMemorySize, SM256);

    // graph build
    k_init<<<NN / 256, 256>>>((const long long*)ei);
    k_count<<<EE / 256, 256>>>(ei);
    k_scan<<<1, 1024>>>();
    k_fill<<<EE / 256, 256>>>(ei);

    // scale x -> fp16
    k_scalex<<<NN * 64 / 256, 256>>>(x);

    // layer 0
    k_gather<64, 0><<<NN, 64>>>();
    k_gemm<128><<<dim3(NN / 128, 2), 256, SM128>>>(W0, b0);

    // layer 1
    k_gather<128, 1><<<NN, 128>>>();
    k_gemm<256><<<dim3(NN / 128, 2), 256, SM256>>>(W1, b1);

    // layer 2
    k_gather<128, 1><<<NN, 128>>>();
    k_gemm<256><<<dim3(NN / 128, 2), 256, SM256>>>(W2, b2);

    // head
    k_uv<<<1, HD>>>(oW, ob, eW, eb);
    k_dots<<<NN / 8, 256>>>();
    k_logits<<<dim3(2, NN), 256>>>(out);
}